// round 15
// baseline (speedup 1.0000x reference)
#include <cuda_runtime.h>
#include <cuda_fp16.h>
#include <stdint.h>
#include <math.h>

// Problem constants
#define BB     4
#define LL     2048
#define DMODEL 1024
#define EI     2048
#define NSTATE 16
#define DCONV  4
#define DTRANK 64
#define DFF    4096
#define MROWS  (BB*LL)           // 8192
#define XDBLW  (DTRANK+2*NSTATE) // 96

typedef __half fp16;

// -------- fp32 scratch --------
__device__ float g_xz  [(size_t)MROWS*2*EI];
__device__ float g_uc  [(size_t)MROWS*EI];
__device__ float g_xdbl[(size_t)MROWS*XDBLW];
__device__ float g_dt  [(size_t)MROWS*EI];
// -------- planar fp16 activation splits: hi / lo --------
__device__ fp16 g_xsh  [(size_t)MROWS*DMODEL];
__device__ fp16 g_xsl  [(size_t)MROWS*DMODEL];
__device__ fp16 g_uch  [(size_t)MROWS*EI];
__device__ fp16 g_ucl  [(size_t)MROWS*EI];
__device__ fp16 g_xdblh[(size_t)MROWS*DTRANK];
__device__ fp16 g_xdbll[(size_t)MROWS*DTRANK];
__device__ fp16 g_ysh  [(size_t)MROWS*EI];
__device__ fp16 g_ysl  [(size_t)MROWS*EI];
__device__ fp16 g_y2sh [(size_t)MROWS*DMODEL];
__device__ fp16 g_y2sl [(size_t)MROWS*DMODEL];
__device__ fp16 g_hsh  [(size_t)MROWS*DFF];
__device__ fp16 g_hsl  [(size_t)MROWS*DFF];
// -------- single-plane fp16 weights --------
__device__ fp16 g_win [(size_t)(2*EI)*DMODEL];
__device__ fp16 g_wxp [(size_t)XDBLW*EI];
__device__ fp16 g_wdt [(size_t)EI*DTRANK];
__device__ fp16 g_wout[(size_t)DMODEL*EI];
__device__ fp16 g_wl1 [(size_t)DFF*DMODEL];
__device__ fp16 g_wl2 [(size_t)DMODEL*DFF];

// ------- GEMM: 128x128 block, 8 warps (256 thr) of 32x64 tiles, 2 CTA/SM -------
#define TM 128
#define TN 128
#define KC 32
#define SKW 40
#define PL (128*SKW)               // elems per plane (5120)
#define STG_ELEMS (3*PL)           // Ah | Al | B
#define STAGES 3
#define GSMEM (STAGES*STG_ELEMS*2) // 92160 B -> 2 CTAs/SM

// ---------------- PTX helpers ----------------
__device__ __forceinline__ void ldsm4(unsigned& r0, unsigned& r1, unsigned& r2, unsigned& r3,
                                      const void* p)
{
    unsigned a = (unsigned)__cvta_generic_to_shared(p);
    asm volatile("ldmatrix.sync.aligned.m8n8.x4.shared.b16 {%0,%1,%2,%3}, [%4];\n"
                 : "=r"(r0), "=r"(r1), "=r"(r2), "=r"(r3) : "r"(a));
}
__device__ __forceinline__ void mma16816(float* d, const unsigned* a, const unsigned* b)
{
    asm volatile(
        "mma.sync.aligned.m16n8k16.row.col.f32.f16.f16.f32 "
        "{%0,%1,%2,%3}, {%4,%5,%6,%7}, {%8,%9}, {%0,%1,%2,%3};\n"
        : "+f"(d[0]), "+f"(d[1]), "+f"(d[2]), "+f"(d[3])
        : "r"(a[0]), "r"(a[1]), "r"(a[2]), "r"(a[3]), "r"(b[0]), "r"(b[1]));
}
__device__ __forceinline__ void cpa16(void* s, const void* g)
{
    unsigned sa = (unsigned)__cvta_generic_to_shared(s);
    asm volatile("cp.async.cg.shared.global [%0], [%1], 16;\n" :: "r"(sa), "l"(g));
}
__device__ __forceinline__ void cpa16z(void* s, const void* g, bool pred)
{
    unsigned sa = (unsigned)__cvta_generic_to_shared(s);
    int sz = pred ? 16 : 0;
    asm volatile("cp.async.cg.shared.global [%0], [%1], 16, %2;\n" :: "r"(sa), "l"(g), "r"(sz));
}
__device__ __forceinline__ void cp_commit() { asm volatile("cp.async.commit_group;\n"); }

template<int EPI>
__device__ __forceinline__ float epi_apply(float v, const float* bias, int n)
{
    if (EPI == 1)      v = fmaxf(v + bias[n], 0.f);
    else if (EPI == 2) v = v + bias[n];
    else if (EPI == 3) { v += bias[n]; v = (v > 20.f) ? v : log1pf(expf(v)); }
    return v;
}

// ---------------- split kernels (planar) ----------------
__global__ void split_a_kernel(const float* __restrict__ A,
                               fp16* __restrict__ AH, fp16* __restrict__ AL, size_t total)
{
    size_t idx = (size_t)blockIdx.x * blockDim.x + threadIdx.x;
    if (idx >= total) return;
    float v = A[idx];
    fp16 h = __float2half(v);
    AH[idx] = h;
    AL[idx] = __float2half(v - __half2float(h));
}
__global__ void split_w_kernel(const float* __restrict__ W, fp16* __restrict__ WS, size_t total)
{
    size_t idx = (size_t)blockIdx.x * blockDim.x + threadIdx.x;
    if (idx >= total) return;
    WS[idx] = __float2half(W[idx]);
}

// ------------- planar fp16-pair GEMM: C[M,Nv] = (Ah+Al)[M,K] * W[Nv,K]^T -------------
// 8 warps of 32x64 (4 M-strips x 2 N-halves), 256 threads, 2 CTAs/SM -> 16 warps/SM.
template<int EPI>
__global__ void __launch_bounds__(256, 2)
gemm_mma(const fp16* __restrict__ Ah, const fp16* __restrict__ Al,
         const fp16* __restrict__ W, const float* __restrict__ bias,
         float* __restrict__ C, fp16* __restrict__ CSh, fp16* __restrict__ CSl,
         int Nv, int Nsplit, int K)
{
    extern __shared__ fp16 sm[];
    const int tid  = threadIdx.x;
    const int lane = tid & 31;
    const int w    = tid >> 5;           // 0..7
    const int bm   = blockIdx.y * TM;
    const int bn   = blockIdx.x * TN;
    const int wm   = (w & 3) * 32;       // 4 M-strips of 32
    const int wn   = (w >> 2) * 64;      // 2 N-halves of 64

    const int a_r = lane & 15, a_c = (lane >> 4) * 8;
    const int b_r = (lane & 7) + ((lane >> 4) << 3), b_c = ((lane >> 3) & 1) * 8;

    float acc[2][8][4];
#pragma unroll
    for (int i = 0; i < 2; i++)
#pragma unroll
        for (int j = 0; j < 8; j++)
#pragma unroll
            for (int q = 0; q < 4; q++) acc[i][j][q] = 0.f;

    const int nk = K / KC;

    // fill: 3 planes x 512 16B-segs; 256 thr -> 2 segs/plane/thread
    auto fill = [&](int kc, int st) {
        fp16* sAh = sm + st * STG_ELEMS;
        fp16* sAl = sAh + PL;
        fp16* sB  = sAl + PL;
#pragma unroll
        for (int i = 0; i < 2; i++) {
            int s = tid + i * 256;
            int row = s >> 2, c = (s & 3) * 8;
            size_t go = (size_t)(bm + row) * K + kc * KC + c;
            cpa16(&sAh[row * SKW + c], Ah + go);
            cpa16(&sAl[row * SKW + c], Al + go);
            bool ok = (bn + row) < Nv;
            cpa16z(&sB[row * SKW + c],
                   W + (size_t)(ok ? (bn + row) : 0) * K + kc * KC + c, ok);
        }
        cp_commit();
    };

    fill(0, 0);
    if (nk > 1) fill(1, 1);

    for (int kb = 0; kb < nk; kb++) {
        if (kb + 2 < nk) { fill(kb + 2, (kb + 2) % STAGES); asm volatile("cp.async.wait_group 2;\n"); }
        else if (kb + 1 < nk) asm volatile("cp.async.wait_group 1;\n");
        else asm volatile("cp.async.wait_group 0;\n");
        __syncthreads();

        fp16* sAh = sm + (kb % STAGES) * STG_ELEMS;
        fp16* sAl = sAh + PL;
        fp16* sB  = sAl + PL;
#pragma unroll
        for (int kk = 0; kk < KC; kk += 16) {
            unsigned bf[4][4];
#pragma unroll
            for (int p = 0; p < 4; p++)
                ldsm4(bf[p][0], bf[p][1], bf[p][2], bf[p][3],
                      &sB[(wn + p * 16 + b_r) * SKW + kk + b_c]);
            unsigned ah[2][4], al[2][4];
#pragma unroll
            for (int mi = 0; mi < 2; mi++) {
                int ro = (wm + mi * 16 + a_r) * SKW + kk + a_c;
                ldsm4(ah[mi][0], ah[mi][1], ah[mi][2], ah[mi][3], &sAh[ro]);
                ldsm4(al[mi][0], al[mi][1], al[mi][2], al[mi][3], &sAl[ro]);
            }
#pragma unroll
            for (int mi = 0; mi < 2; mi++)
#pragma unroll
                for (int p = 0; p < 4; p++) {
                    mma16816(acc[mi][2 * p],     ah[mi], bf[p]);
                    mma16816(acc[mi][2 * p + 1], ah[mi], bf[p] + 2);
                }
#pragma unroll
            for (int mi = 0; mi < 2; mi++)
#pragma unroll
                for (int p = 0; p < 4; p++) {
                    mma16816(acc[mi][2 * p],     al[mi], bf[p]);
                    mma16816(acc[mi][2 * p + 1], al[mi], bf[p] + 2);
                }
        }
        __syncthreads();
    }

    const int grp = lane >> 2, tq = lane & 3;
#pragma unroll
    for (int mi = 0; mi < 2; mi++)
#pragma unroll
        for (int nj = 0; nj < 8; nj++) {
            float* d = acc[mi][nj];
            int r0 = bm + wm + mi * 16 + grp;
            int c  = bn + wn + nj * 8 + tq * 2;
#pragma unroll
            for (int q = 0; q < 4; q++) {
                int r = r0 + (q >> 1) * 8;
                int cc = c + (q & 1);
                if (cc < Nv) {
                    float v = epi_apply<EPI>(d[q], bias, cc);
                    if (C) C[(size_t)r * Nv + cc] = v;
                    if (CSh && cc < Nsplit) {
                        fp16 h = __float2half(v);
                        size_t o = (size_t)r * Nsplit + cc;
                        CSh[o] = h;
                        CSl[o] = __float2half(v - __half2float(h));
                    }
                }
            }
        }
}

// ---------------- conv + silu: smem-tiled, coalesced ----------------
#define CBR 32
#define CBE 64
__global__ void __launch_bounds__(256)
conv_silu_kernel(const float* __restrict__ conv_w, const float* __restrict__ conv_b)
{
    __shared__ float su[CBR + 3][CBE];
    const int e0 = blockIdx.x * CBE;
    const int r0 = blockIdx.y * CBR;
    const int t  = threadIdx.x;
    const int te = t & (CBE - 1);
    const int bbase = (r0 / LL) * LL;

#pragma unroll
    for (int i = t >> 6; i < CBR + 3; i += 4) {
        int gr = r0 - 3 + i;
        su[i][te] = (gr >= bbase) ? g_xz[(size_t)gr * (2 * EI) + e0 + te] : 0.f;
    }
    __syncthreads();

    const int e = e0 + te;
    const float w0 = conv_w[e * DCONV], w1 = conv_w[e * DCONV + 1];
    const float w2 = conv_w[e * DCONV + 2], w3 = conv_w[e * DCONV + 3];
    const float bv = conv_b[e];
#pragma unroll
    for (int i = t >> 6; i < CBR; i += 4) {
        float s = bv + w0 * su[i][te] + w1 * su[i + 1][te]
                     + w2 * su[i + 2][te] + w3 * su[i + 3][te];
        float v = s / (1.f + expf(-s));
        size_t row = (size_t)(r0 + i);
        g_uc[row * EI + e] = v;
        fp16 h = __float2half(v);
        size_t o = row * EI + e;
        g_uch[o] = h;
        g_ucl[o] = __float2half(v - __half2float(h));
    }
}

// ---------------- selective scan: smem-staged, coalesced ----------------
#define SCH 64
__global__ void __launch_bounds__(512)
scan_kernel(const float* __restrict__ A_log, const float* __restrict__ Dp)
{
    __shared__ float s_dt[SCH][32], s_uc[SCH][32], s_z[SCH][32],
                     s_bc[SCH][32], s_y[SCH][32];
    const int b  = blockIdx.y;
    const int e0 = blockIdx.x * 32;
    const int t  = threadIdx.x;
    const int c  = t >> 4;
    const int n  = t & 15;
    const int e  = e0 + c;

    const float Aen = -expf(A_log[e * NSTATE + n]);
    const float Dv  = Dp[e];
    float h = 0.f;
    const size_t rb = (size_t)b * LL;

    for (int l0 = 0; l0 < LL; l0 += SCH) {
        for (int k = t; k < SCH * 32; k += 512) {
            int i = k >> 5, j = k & 31;
            size_t row = rb + l0 + i;
            s_dt[i][j] = g_dt[row * EI + e0 + j];
            s_uc[i][j] = g_uc[row * EI + e0 + j];
            s_z [i][j] = g_xz[row * (2 * EI) + EI + e0 + j];
            s_bc[i][j] = g_xdbl[row * XDBLW + DTRANK + j];
        }
        __syncthreads();

#pragma unroll 4
        for (int i = 0; i < SCH; i++) {
            float dtv = s_dt[i][c];
            float uv  = s_uc[i][c];
            float Bt  = s_bc[i][n];
            float Ct  = s_bc[i][16 + n];
            h = expf(dtv * Aen) * h + dtv * uv * Bt;
            float p = h * Ct;
            p += __shfl_xor_sync(0xffffffffu, p, 8);
            p += __shfl_xor_sync(0xffffffffu, p, 4);
            p += __shfl_xor_sync(0xffffffffu, p, 2);
            p += __shfl_xor_sync(0xffffffffu, p, 1);
            if (n == 0) {
                float zv = s_z[i][c];
                s_y[i][c] = (p + uv * Dv) * (zv / (1.f + expf(-zv)));
            }
        }
        __syncthreads();

        for (int k = t; k < SCH * 32; k += 512) {
            int i = k >> 5, j = k & 31;
            float yv = s_y[i][j];
            size_t row = rb + l0 + i;
            fp16 hh = __float2half(yv);
            size_t o = row * EI + e0 + j;
            g_ysh[o] = hh;
            g_ysl[o] = __float2half(yv - __half2float(hh));
        }
        __syncthreads();
    }
}

// ---------------- host launch ----------------
extern "C" void kernel_launch(void* const* d_in, const int* in_sizes, int n_in,
                              void* d_out, int out_size)
{
    const float* x          = (const float*)d_in[0];
    const float* in_proj_w  = (const float*)d_in[1];
    const float* conv_w     = (const float*)d_in[2];
    const float* conv_b     = (const float*)d_in[3];
    const float* x_proj_w   = (const float*)d_in[4];
    const float* dt_proj_w  = (const float*)d_in[5];
    const float* dt_proj_b  = (const float*)d_in[6];
    const float* A_log      = (const float*)d_in[7];
    const float* Dp         = (const float*)d_in[8];
    const float* out_proj_w = (const float*)d_in[9];
    const float* lin1_w     = (const float*)d_in[10];
    const float* lin1_b     = (const float*)d_in[11];
    const float* lin2_w     = (const float*)d_in[12];
    const float* lin2_b     = (const float*)d_in[13];
    float* out = (float*)d_out;

    float *p_xz, *p_xdbl, *p_dt;
    fp16 *p_xsh,*p_xsl,*p_uch,*p_ucl,*p_xdh,*p_xdl,*p_ysh,*p_ysl,*p_y2h,*p_y2l,*p_hsh,*p_hsl;
    fp16 *p_win,*p_wxp,*p_wdt,*p_wout,*p_wl1,*p_wl2;
    cudaGetSymbolAddress((void**)&p_xz,   g_xz);
    cudaGetSymbolAddress((void**)&p_xdbl, g_xdbl);
    cudaGetSymbolAddress((void**)&p_dt,   g_dt);
    cudaGetSymbolAddress((void**)&p_xsh,  g_xsh);  cudaGetSymbolAddress((void**)&p_xsl, g_xsl);
    cudaGetSymbolAddress((void**)&p_uch,  g_uch);  cudaGetSymbolAddress((void**)&p_ucl, g_ucl);
    cudaGetSymbolAddress((void**)&p_xdh,  g_xdblh);cudaGetSymbolAddress((void**)&p_xdl, g_xdbll);
    cudaGetSymbolAddress((void**)&p_ysh,  g_ysh);  cudaGetSymbolAddress((void**)&p_ysl, g_ysl);
    cudaGetSymbolAddress((void**)&p_y2h,  g_y2sh); cudaGetSymbolAddress((void**)&p_y2l, g_y2sl);
    cudaGetSymbolAddress((void**)&p_hsh,  g_hsh);  cudaGetSymbolAddress((void**)&p_hsl, g_hsl);
    cudaGetSymbolAddress((void**)&p_win,  g_win);
    cudaGetSymbolAddress((void**)&p_wxp,  g_wxp);
    cudaGetSymbolAddress((void**)&p_wdt,  g_wdt);
    cudaGetSymbolAddress((void**)&p_wout, g_wout);
    cudaGetSymbolAddress((void**)&p_wl1,  g_wl1);
    cudaGetSymbolAddress((void**)&p_wl2,  g_wl2);

    cudaFuncSetAttribute(gemm_mma<0>, cudaFuncAttributeMaxDynamicSharedMemorySize, GSMEM);
    cudaFuncSetAttribute(gemm_mma<1>, cudaFuncAttributeMaxDynamicSharedMemorySize, GSMEM);
    cudaFuncSetAttribute(gemm_mma<2>, cudaFuncAttributeMaxDynamicSharedMemorySize, GSMEM);
    cudaFuncSetAttribute(gemm_mma<3>, cudaFuncAttributeMaxDynamicSharedMemorySize, GSMEM);

    const int GY = MROWS / TM;   // 64
    size_t t;

    // idx 0-2; idx 3 = in_proj GEMM (profiled)
    t = (size_t)MROWS * DMODEL;
    split_a_kernel<<<(unsigned)((t + 255) / 256), 256>>>(x, p_xsh, p_xsl, t);
    t = (size_t)(2 * EI) * DMODEL;
    split_w_kernel<<<(unsigned)((t + 255) / 256), 256>>>(in_proj_w, p_win, t);
    t = (size_t)XDBLW * EI;
    split_w_kernel<<<(unsigned)((t + 255) / 256), 256>>>(x_proj_w, p_wxp, t);

    // idx3: xz = x @ in_proj_w^T -> fp32 g_xz   (PROFILED)
    gemm_mma<0><<<dim3((2 * EI) / TN, GY), 256, GSMEM>>>(
        p_xsh, p_xsl, p_win, (const float*)0, p_xz, (fp16*)0, (fp16*)0,
        2 * EI, 0, DMODEL);

    // conv + silu
    conv_silu_kernel<<<dim3(EI / CBE, MROWS / CBR), 256>>>(conv_w, conv_b);

    t = (size_t)EI * DTRANK;
    split_w_kernel<<<(unsigned)((t + 255) / 256), 256>>>(dt_proj_w, p_wdt, t);

    // x_dbl = uc @ x_proj_w^T -> fp32 g_xdbl + planar split of dt cols
    gemm_mma<0><<<dim3(1, GY), 256, GSMEM>>>(
        p_uch, p_ucl, p_wxp, (const float*)0, p_xdbl, p_xdh, p_xdl,
        XDBLW, DTRANK, EI);

    // dt = softplus(dt_raw @ dt_proj_w^T + b) -> fp32 g_dt
    gemm_mma<3><<<dim3(EI / TN, GY), 256, GSMEM>>>(
        p_xdh, p_xdl, p_wdt, dt_proj_b, p_dt, (fp16*)0, (fp16*)0,
        EI, 0, DTRANK);

    // selective scan -> planar ys
    scan_kernel<<<dim3(EI / 32, BB), 512>>>(A_log, Dp);

    t = (size_t)DMODEL * EI;
    split_w_kernel<<<(unsigned)((t + 255) / 256), 256>>>(out_proj_w, p_wout, t);

    // y2 = y @ out_proj_w^T -> planar y2s only
    gemm_mma<0><<<dim3(DMODEL / TN, GY), 256, GSMEM>>>(
        p_ysh, p_ysl, p_wout, (const float*)0, (float*)0, p_y2h, p_y2l,
        DMODEL, DMODEL, EI);

    t = (size_t)DFF * DMODEL;
    split_w_kernel<<<(unsigned)((t + 255) / 256), 256>>>(lin1_w, p_wl1, t);

    // h = relu(y2 @ lin1_w^T + b) -> planar hs only
    gemm_mma<1><<<dim3(DFF / TN, GY), 256, GSMEM>>>(
        p_y2h, p_y2l, p_wl1, lin1_b, (float*)0, p_hsh, p_hsl,
        DFF, DFF, DMODEL);

    t = (size_t)DMODEL * DFF;
    split_w_kernel<<<(unsigned)((t + 255) / 256), 256>>>(lin2_w, p_wl2, t);

    // out = h @ lin2_w^T + b -> fp32 out
    gemm_mma<2><<<dim3(DMODEL / TN, GY), 256, GSMEM>>>(
        p_hsh, p_hsl, p_wl2, lin2_b, out, (fp16*)0, (fp16*)0,
        DMODEL, 0, DFF);
}

// round 16
// speedup vs baseline: 1.2743x; 1.2743x over previous
#include <cuda_runtime.h>
#include <cuda_fp16.h>
#include <stdint.h>
#include <math.h>

// Problem constants
#define BB     4
#define LL     2048
#define DMODEL 1024
#define EI     2048
#define NSTATE 16
#define DCONV  4
#define DTRANK 64
#define DFF    4096
#define MROWS  (BB*LL)           // 8192
#define XDBLW  (DTRANK+2*NSTATE) // 96

typedef __half fp16;

// -------- fp32 scratch --------
__device__ float g_xz  [(size_t)MROWS*2*EI];
__device__ float g_uc  [(size_t)MROWS*EI];
__device__ float g_xdbl[(size_t)MROWS*XDBLW];
__device__ float g_dt  [(size_t)MROWS*EI];
// -------- planar fp16 activation splits --------
__device__ fp16 g_xsh  [(size_t)MROWS*DMODEL];
__device__ fp16 g_xsl  [(size_t)MROWS*DMODEL];
__device__ fp16 g_uch  [(size_t)MROWS*EI];
__device__ fp16 g_ucl  [(size_t)MROWS*EI];
__device__ fp16 g_xdblh[(size_t)MROWS*DTRANK];
__device__ fp16 g_xdbll[(size_t)MROWS*DTRANK];
__device__ fp16 g_ysh  [(size_t)MROWS*EI];
__device__ fp16 g_y2sh [(size_t)MROWS*DMODEL];
__device__ fp16 g_hsh  [(size_t)MROWS*DFF];
// -------- single-plane fp16 weights --------
__device__ fp16 g_win [(size_t)(2*EI)*DMODEL];
__device__ fp16 g_wxp [(size_t)XDBLW*EI];
__device__ fp16 g_wdt [(size_t)EI*DTRANK];
__device__ fp16 g_wout[(size_t)DMODEL*EI];
__device__ fp16 g_wl1 [(size_t)DFF*DMODEL];
__device__ fp16 g_wl2 [(size_t)DMODEL*DFF];

// ------- GEMM: 128x128 block, 4 warps (128 thr), 64x64 warp tiles, 2 CTA/SM -------
#define TM 128
#define TN 128
#define KC 32
#define SKW 40
#define PL (128*SKW)               // elems per plane (5120)
#define STG_ELEMS (3*PL)           // max planes: Ah | Al | B
#define STAGES 3
#define GSMEM (STAGES*STG_ELEMS*2) // 92160 B -> 2 CTAs/SM

// ---------------- PTX helpers ----------------
__device__ __forceinline__ void ldsm4(unsigned& r0, unsigned& r1, unsigned& r2, unsigned& r3,
                                      const void* p)
{
    unsigned a = (unsigned)__cvta_generic_to_shared(p);
    asm volatile("ldmatrix.sync.aligned.m8n8.x4.shared.b16 {%0,%1,%2,%3}, [%4];\n"
                 : "=r"(r0), "=r"(r1), "=r"(r2), "=r"(r3) : "r"(a));
}
__device__ __forceinline__ void mma16816(float* d, const unsigned* a, const unsigned* b)
{
    asm volatile(
        "mma.sync.aligned.m16n8k16.row.col.f32.f16.f16.f32 "
        "{%0,%1,%2,%3}, {%4,%5,%6,%7}, {%8,%9}, {%0,%1,%2,%3};\n"
        : "+f"(d[0]), "+f"(d[1]), "+f"(d[2]), "+f"(d[3])
        : "r"(a[0]), "r"(a[1]), "r"(a[2]), "r"(a[3]), "r"(b[0]), "r"(b[1]));
}
__device__ __forceinline__ void cpa16(void* s, const void* g)
{
    unsigned sa = (unsigned)__cvta_generic_to_shared(s);
    asm volatile("cp.async.cg.shared.global [%0], [%1], 16;\n" :: "r"(sa), "l"(g));
}
__device__ __forceinline__ void cpa16z(void* s, const void* g, bool pred)
{
    unsigned sa = (unsigned)__cvta_generic_to_shared(s);
    int sz = pred ? 16 : 0;
    asm volatile("cp.async.cg.shared.global [%0], [%1], 16, %2;\n" :: "r"(sa), "l"(g), "r"(sz));
}
__device__ __forceinline__ void cp_commit() { asm volatile("cp.async.commit_group;\n"); }

template<int EPI>
__device__ __forceinline__ float epi_apply(float v, const float* bias, int n)
{
    if (EPI == 1)      v = fmaxf(v + bias[n], 0.f);
    else if (EPI == 2) v = v + bias[n];
    else if (EPI == 3) { v += bias[n]; v = (v > 20.f) ? v : log1pf(expf(v)); }
    return v;
}

// ---------------- split kernels (planar) ----------------
__global__ void split_a_kernel(const float* __restrict__ A,
                               fp16* __restrict__ AH, fp16* __restrict__ AL, size_t total)
{
    size_t idx = (size_t)blockIdx.x * blockDim.x + threadIdx.x;
    if (idx >= total) return;
    float v = A[idx];
    fp16 h = __float2half(v);
    AH[idx] = h;
    AL[idx] = __float2half(v - __half2float(h));
}
__global__ void split_w_kernel(const float* __restrict__ W, fp16* __restrict__ WS, size_t total)
{
    size_t idx = (size_t)blockIdx.x * blockDim.x + threadIdx.x;
    if (idx >= total) return;
    WS[idx] = __float2half(W[idx]);
}

// ------------- planar fp16 GEMM: C = (Ah [+ Al]) * W^T -------------
// LO=true: two-pass (hi+lo) A; LO=false: hi-only A (half the MMAs, 2 smem planes).
template<int EPI, bool LO>
__global__ void __launch_bounds__(128, 2)
gemm_mma(const fp16* __restrict__ Ah, const fp16* __restrict__ Al,
         const fp16* __restrict__ W, const float* __restrict__ bias,
         float* __restrict__ C, fp16* __restrict__ CSh, fp16* __restrict__ CSl,
         int Nv, int Nsplit, int K)
{
    extern __shared__ fp16 sm[];
    const int tid  = threadIdx.x;
    const int lane = tid & 31;
    const int w    = tid >> 5;
    const int bm   = blockIdx.y * TM;
    const int bn   = blockIdx.x * TN;
    const int wm   = (w & 1) * 64;
    const int wn   = (w >> 1) * 64;

    const int a_r = lane & 15, a_c = (lane >> 4) * 8;
    const int b_r = (lane & 7) + ((lane >> 4) << 3), b_c = ((lane >> 3) & 1) * 8;

    const int NPLANES = LO ? 3 : 2;
    const int STG = NPLANES * PL;

    float acc[4][8][4];
#pragma unroll
    for (int i = 0; i < 4; i++)
#pragma unroll
        for (int j = 0; j < 8; j++)
#pragma unroll
            for (int q = 0; q < 4; q++) acc[i][j][q] = 0.f;

    const int nk = K / KC;

    auto fill = [&](int kc, int st) {
        fp16* sAh = sm + st * STG;
        fp16* sAl = sAh + PL;                      // only valid if LO
        fp16* sB  = sAh + (NPLANES - 1) * PL;      // last plane
#pragma unroll
        for (int i = 0; i < 4; i++) {
            int s = tid + i * 128;
            int row = s >> 2, c = (s & 3) * 8;
            size_t go = (size_t)(bm + row) * K + kc * KC + c;
            cpa16(&sAh[row * SKW + c], Ah + go);
            if (LO) cpa16(&sAl[row * SKW + c], Al + go);
            bool ok = (bn + row) < Nv;
            cpa16z(&sB[row * SKW + c],
                   W + (size_t)(ok ? (bn + row) : 0) * K + kc * KC + c, ok);
        }
        cp_commit();
    };

    fill(0, 0);
    if (nk > 1) fill(1, 1);

    for (int kb = 0; kb < nk; kb++) {
        if (kb + 2 < nk) { fill(kb + 2, (kb + 2) % STAGES); asm volatile("cp.async.wait_group 2;\n"); }
        else if (kb + 1 < nk) asm volatile("cp.async.wait_group 1;\n");
        else asm volatile("cp.async.wait_group 0;\n");
        __syncthreads();

        fp16* sAh = sm + (kb % STAGES) * STG;
        fp16* sAl = sAh + PL;
        fp16* sB  = sAh + (NPLANES - 1) * PL;
#pragma unroll
        for (int kk = 0; kk < KC; kk += 16) {
            unsigned bf[4][4];
#pragma unroll
            for (int p = 0; p < 4; p++)
                ldsm4(bf[p][0], bf[p][1], bf[p][2], bf[p][3],
                      &sB[(wn + p * 16 + b_r) * SKW + kk + b_c]);
            unsigned ah[4][4];
#pragma unroll
            for (int mi = 0; mi < 4; mi++)
                ldsm4(ah[mi][0], ah[mi][1], ah[mi][2], ah[mi][3],
                      &sAh[(wm + mi * 16 + a_r) * SKW + kk + a_c]);
#pragma unroll
            for (int mi = 0; mi < 4; mi++)
#pragma unroll
                for (int p = 0; p < 4; p++) {
                    mma16816(acc[mi][2 * p],     ah[mi], bf[p]);
                    mma16816(acc[mi][2 * p + 1], ah[mi], bf[p] + 2);
                }
            if (LO) {
                unsigned al[4][4];
#pragma unroll
                for (int mi = 0; mi < 4; mi++)
                    ldsm4(al[mi][0], al[mi][1], al[mi][2], al[mi][3],
                          &sAl[(wm + mi * 16 + a_r) * SKW + kk + a_c]);
#pragma unroll
                for (int mi = 0; mi < 4; mi++)
#pragma unroll
                    for (int p = 0; p < 4; p++) {
                        mma16816(acc[mi][2 * p],     al[mi], bf[p]);
                        mma16816(acc[mi][2 * p + 1], al[mi], bf[p] + 2);
                    }
            }
        }
        __syncthreads();
    }

    const int grp = lane >> 2, tq = lane & 3;
#pragma unroll
    for (int mi = 0; mi < 4; mi++)
#pragma unroll
        for (int nj = 0; nj < 8; nj++) {
            float* d = acc[mi][nj];
            int r0 = bm + wm + mi * 16 + grp;
            int c  = bn + wn + nj * 8 + tq * 2;
#pragma unroll
            for (int q = 0; q < 4; q++) {
                int r = r0 + (q >> 1) * 8;
                int cc = c + (q & 1);
                if (cc < Nv) {
                    float v = epi_apply<EPI>(d[q], bias, cc);
                    if (C) C[(size_t)r * Nv + cc] = v;
                    if (CSh && cc < Nsplit) {
                        fp16 h = __float2half(v);
                        size_t o = (size_t)r * Nsplit + cc;
                        CSh[o] = h;
                        if (CSl) CSl[o] = __float2half(v - __half2float(h));
                    }
                }
            }
        }
}

// ---------------- conv + silu: smem-tiled, coalesced ----------------
#define CBR 32
#define CBE 64
__global__ void __launch_bounds__(256)
conv_silu_kernel(const float* __restrict__ conv_w, const float* __restrict__ conv_b)
{
    __shared__ float su[CBR + 3][CBE];
    const int e0 = blockIdx.x * CBE;
    const int r0 = blockIdx.y * CBR;
    const int t  = threadIdx.x;
    const int te = t & (CBE - 1);
    const int bbase = (r0 / LL) * LL;

#pragma unroll
    for (int i = t >> 6; i < CBR + 3; i += 4) {
        int gr = r0 - 3 + i;
        su[i][te] = (gr >= bbase) ? g_xz[(size_t)gr * (2 * EI) + e0 + te] : 0.f;
    }
    __syncthreads();

    const int e = e0 + te;
    const float w0 = conv_w[e * DCONV], w1 = conv_w[e * DCONV + 1];
    const float w2 = conv_w[e * DCONV + 2], w3 = conv_w[e * DCONV + 3];
    const float bv = conv_b[e];
#pragma unroll
    for (int i = t >> 6; i < CBR; i += 4) {
        float s = bv + w0 * su[i][te] + w1 * su[i + 1][te]
                     + w2 * su[i + 2][te] + w3 * su[i + 3][te];
        float v = s / (1.f + expf(-s));
        size_t row = (size_t)(r0 + i);
        g_uc[row * EI + e] = v;
        fp16 h = __float2half(v);
        size_t o = row * EI + e;
        g_uch[o] = h;
        g_ucl[o] = __float2half(v - __half2float(h));
    }
}

// ---------------- selective scan: smem-staged, coalesced ----------------
#define SCH 64
__global__ void __launch_bounds__(512)
scan_kernel(const float* __restrict__ A_log, const float* __restrict__ Dp)
{
    __shared__ float s_dt[SCH][32], s_uc[SCH][32], s_z[SCH][32],
                     s_bc[SCH][32], s_y[SCH][32];
    const int b  = blockIdx.y;
    const int e0 = blockIdx.x * 32;
    const int t  = threadIdx.x;
    const int c  = t >> 4;
    const int n  = t & 15;
    const int e  = e0 + c;

    const float Aen = -expf(A_log[e * NSTATE + n]);
    const float Dv  = Dp[e];
    float h = 0.f;
    const size_t rb = (size_t)b * LL;

    for (int l0 = 0; l0 < LL; l0 += SCH) {
        for (int k = t; k < SCH * 32; k += 512) {
            int i = k >> 5, j = k & 31;
            size_t row = rb + l0 + i;
            s_dt[i][j] = g_dt[row * EI + e0 + j];
            s_uc[i][j] = g_uc[row * EI + e0 + j];
            s_z [i][j] = g_xz[row * (2 * EI) + EI + e0 + j];
            s_bc[i][j] = g_xdbl[row * XDBLW + DTRANK + j];
        }
        __syncthreads();

#pragma unroll 4
        for (int i = 0; i < SCH; i++) {
            float dtv = s_dt[i][c];
            float uv  = s_uc[i][c];
            float Bt  = s_bc[i][n];
            float Ct  = s_bc[i][16 + n];
            h = expf(dtv * Aen) * h + dtv * uv * Bt;
            float p = h * Ct;
            p += __shfl_xor_sync(0xffffffffu, p, 8);
            p += __shfl_xor_sync(0xffffffffu, p, 4);
            p += __shfl_xor_sync(0xffffffffu, p, 2);
            p += __shfl_xor_sync(0xffffffffu, p, 1);
            if (n == 0) {
                float zv = s_z[i][c];
                s_y[i][c] = (p + uv * Dv) * (zv / (1.f + expf(-zv)));
            }
        }
        __syncthreads();

        // out_proj is hi-only: write ysh only
        for (int k = t; k < SCH * 32; k += 512) {
            int i = k >> 5, j = k & 31;
            size_t row = rb + l0 + i;
            g_ysh[row * EI + e0 + j] = __float2half(s_y[i][j]);
        }
        __syncthreads();
    }
}

// ---------------- host launch ----------------
extern "C" void kernel_launch(void* const* d_in, const int* in_sizes, int n_in,
                              void* d_out, int out_size)
{
    const float* x          = (const float*)d_in[0];
    const float* in_proj_w  = (const float*)d_in[1];
    const float* conv_w     = (const float*)d_in[2];
    const float* conv_b     = (const float*)d_in[3];
    const float* x_proj_w   = (const float*)d_in[4];
    const float* dt_proj_w  = (const float*)d_in[5];
    const float* dt_proj_b  = (const float*)d_in[6];
    const float* A_log      = (const float*)d_in[7];
    const float* Dp         = (const float*)d_in[8];
    const float* out_proj_w = (const float*)d_in[9];
    const float* lin1_w     = (const float*)d_in[10];
    const float* lin1_b     = (const float*)d_in[11];
    const float* lin2_w     = (const float*)d_in[12];
    const float* lin2_b     = (const float*)d_in[13];
    float* out = (float*)d_out;

    float *p_xz, *p_xdbl, *p_dt;
    fp16 *p_xsh,*p_xsl,*p_uch,*p_ucl,*p_xdh,*p_xdl,*p_ysh,*p_y2h,*p_hsh;
    fp16 *p_win,*p_wxp,*p_wdt,*p_wout,*p_wl1,*p_wl2;
    cudaGetSymbolAddress((void**)&p_xz,   g_xz);
    cudaGetSymbolAddress((void**)&p_xdbl, g_xdbl);
    cudaGetSymbolAddress((void**)&p_dt,   g_dt);
    cudaGetSymbolAddress((void**)&p_xsh,  g_xsh);  cudaGetSymbolAddress((void**)&p_xsl, g_xsl);
    cudaGetSymbolAddress((void**)&p_uch,  g_uch);  cudaGetSymbolAddress((void**)&p_ucl, g_ucl);
    cudaGetSymbolAddress((void**)&p_xdh,  g_xdblh);cudaGetSymbolAddress((void**)&p_xdl, g_xdbll);
    cudaGetSymbolAddress((void**)&p_ysh,  g_ysh);
    cudaGetSymbolAddress((void**)&p_y2h,  g_y2sh);
    cudaGetSymbolAddress((void**)&p_hsh,  g_hsh);
    cudaGetSymbolAddress((void**)&p_win,  g_win);
    cudaGetSymbolAddress((void**)&p_wxp,  g_wxp);
    cudaGetSymbolAddress((void**)&p_wdt,  g_wdt);
    cudaGetSymbolAddress((void**)&p_wout, g_wout);
    cudaGetSymbolAddress((void**)&p_wl1,  g_wl1);
    cudaGetSymbolAddress((void**)&p_wl2,  g_wl2);

    cudaFuncSetAttribute((const void*)gemm_mma<0,true>,  cudaFuncAttributeMaxDynamicSharedMemorySize, GSMEM);
    cudaFuncSetAttribute((const void*)gemm_mma<3,true>,  cudaFuncAttributeMaxDynamicSharedMemorySize, GSMEM);
    cudaFuncSetAttribute((const void*)gemm_mma<0,false>, cudaFuncAttributeMaxDynamicSharedMemorySize, GSMEM);
    cudaFuncSetAttribute((const void*)gemm_mma<1,false>, cudaFuncAttributeMaxDynamicSharedMemorySize, GSMEM);
    cudaFuncSetAttribute((const void*)gemm_mma<2,false>, cudaFuncAttributeMaxDynamicSharedMemorySize, GSMEM);

    const int GY = MROWS / TM;   // 64
    size_t t;

    // idx 0-2; idx 3 = in_proj GEMM (profiled)
    t = (size_t)MROWS * DMODEL;
    split_a_kernel<<<(unsigned)((t + 255) / 256), 256>>>(x, p_xsh, p_xsl, t);
    t = (size_t)(2 * EI) * DMODEL;
    split_w_kernel<<<(unsigned)((t + 255) / 256), 256>>>(in_proj_w, p_win, t);
    t = (size_t)XDBLW * EI;
    split_w_kernel<<<(unsigned)((t + 255) / 256), 256>>>(x_proj_w, p_wxp, t);

    // idx3: xz = x @ in_proj_w^T (hi+lo)  (PROFILED)
    gemm_mma<0,true><<<dim3((2 * EI) / TN, GY), 128, GSMEM>>>(
        p_xsh, p_xsl, p_win, (const float*)0, p_xz, (fp16*)0, (fp16*)0,
        2 * EI, 0, DMODEL);

    // conv + silu
    conv_silu_kernel<<<dim3(EI / CBE, MROWS / CBR), 256>>>(conv_w, conv_b);

    t = (size_t)EI * DTRANK;
    split_w_kernel<<<(unsigned)((t + 255) / 256), 256>>>(dt_proj_w, p_wdt, t);

    // x_dbl = uc @ x_proj_w^T (hi+lo) -> fp32 g_xdbl + planar split of dt cols
    gemm_mma<0,true><<<dim3(1, GY), 128, GSMEM>>>(
        p_uch, p_ucl, p_wxp, (const float*)0, p_xdbl, p_xdh, p_xdl,
        XDBLW, DTRANK, EI);

    // dt = softplus(dt_raw @ dt_proj_w^T + b) (hi+lo)
    gemm_mma<3,true><<<dim3(EI / TN, GY), 128, GSMEM>>>(
        p_xdh, p_xdl, p_wdt, dt_proj_b, p_dt, (fp16*)0, (fp16*)0,
        EI, 0, DTRANK);

    // selective scan -> ysh only
    scan_kernel<<<dim3(EI / 32, BB), 512>>>(A_log, Dp);

    t = (size_t)DMODEL * EI;
    split_w_kernel<<<(unsigned)((t + 255) / 256), 256>>>(out_proj_w, p_wout, t);

    // y2 = y @ out_proj_w^T (hi only) -> y2sh only
    gemm_mma<0,false><<<dim3(DMODEL / TN, GY), 128, GSMEM>>>(
        p_ysh, (const fp16*)0, p_wout, (const float*)0, (float*)0, p_y2h, (fp16*)0,
        DMODEL, DMODEL, EI);

    t = (size_t)DFF * DMODEL;
    split_w_kernel<<<(unsigned)((t + 255) / 256), 256>>>(lin1_w, p_wl1, t);

    // h = relu(y2 @ lin1_w^T + b) (hi only) -> hsh only
    gemm_mma<1,false><<<dim3(DFF / TN, GY), 128, GSMEM>>>(
        p_y2h, (const fp16*)0, p_wl1, lin1_b, (float*)0, p_hsh, (fp16*)0,
        DFF, DFF, DMODEL);

    t = (size_t)DMODEL * DFF;
    split_w_kernel<<<(unsigned)((t + 255) / 256), 256>>>(lin2_w, p_wl2, t);

    // out = h @ lin2_w^T + b (hi only) -> fp32 out
    gemm_mma<2,false><<<dim3(DMODEL / TN, GY), 128, GSMEM>>>(
        p_hsh, (const fp16*)0, p_wl2, lin2_b, out, (fp16*)0, (fp16*)0,
        DMODEL, 0, DFF);
}

// round 17
// speedup vs baseline: 1.4090x; 1.1058x over previous
#include <cuda_runtime.h>
#include <cuda_fp16.h>
#include <stdint.h>
#include <math.h>

// Problem constants
#define BB     4
#define LL     2048
#define DMODEL 1024
#define EI     2048
#define NSTATE 16
#define DCONV  4
#define DTRANK 64
#define DFF    4096
#define MROWS  (BB*LL)           // 8192
#define XDBLW  (DTRANK+2*NSTATE) // 96

typedef __half fp16;

// -------- fp32 scratch --------
__device__ float g_xz   [(size_t)MROWS*2*EI];
__device__ float g_uc   [(size_t)MROWS*EI];
__device__ float g_xdbl [(size_t)MROWS*XDBLW];
__device__ float g_xdblp[(size_t)4*MROWS*XDBLW];   // split-K partials
__device__ float g_dt   [(size_t)MROWS*EI];
// -------- planar fp16 activation splits --------
__device__ fp16 g_xsh  [(size_t)MROWS*DMODEL];
__device__ fp16 g_uch  [(size_t)MROWS*EI];
__device__ fp16 g_ucl  [(size_t)MROWS*EI];
__device__ fp16 g_xdblh[(size_t)MROWS*DTRANK];
__device__ fp16 g_xdbll[(size_t)MROWS*DTRANK];
__device__ fp16 g_ysh  [(size_t)MROWS*EI];
__device__ fp16 g_y2sh [(size_t)MROWS*DMODEL];
__device__ fp16 g_hsh  [(size_t)MROWS*DFF];
// -------- single-plane fp16 weights --------
__device__ fp16 g_win [(size_t)(2*EI)*DMODEL];
__device__ fp16 g_wxp [(size_t)XDBLW*EI];
__device__ fp16 g_wdt [(size_t)EI*DTRANK];
__device__ fp16 g_wout[(size_t)DMODEL*EI];
__device__ fp16 g_wl1 [(size_t)DFF*DMODEL];
__device__ fp16 g_wl2 [(size_t)DMODEL*DFF];

// ------- GEMM: 128x128 block, 4 warps (128 thr), 64x64 warp tiles, 2 CTA/SM -------
#define TM 128
#define TN 128
#define KC 32
#define SKW 40
#define PL (128*SKW)               // elems per plane (5120)
#define STG_ELEMS (3*PL)           // max planes: Ah | Al | B
#define STAGES 3
#define GSMEM (STAGES*STG_ELEMS*2) // 92160 B -> 2 CTAs/SM

// ---------------- PTX helpers ----------------
__device__ __forceinline__ void ldsm4(unsigned& r0, unsigned& r1, unsigned& r2, unsigned& r3,
                                      const void* p)
{
    unsigned a = (unsigned)__cvta_generic_to_shared(p);
    asm volatile("ldmatrix.sync.aligned.m8n8.x4.shared.b16 {%0,%1,%2,%3}, [%4];\n"
                 : "=r"(r0), "=r"(r1), "=r"(r2), "=r"(r3) : "r"(a));
}
__device__ __forceinline__ void mma16816(float* d, const unsigned* a, const unsigned* b)
{
    asm volatile(
        "mma.sync.aligned.m16n8k16.row.col.f32.f16.f16.f32 "
        "{%0,%1,%2,%3}, {%4,%5,%6,%7}, {%8,%9}, {%0,%1,%2,%3};\n"
        : "+f"(d[0]), "+f"(d[1]), "+f"(d[2]), "+f"(d[3])
        : "r"(a[0]), "r"(a[1]), "r"(a[2]), "r"(a[3]), "r"(b[0]), "r"(b[1]));
}
__device__ __forceinline__ void cpa16(void* s, const void* g)
{
    unsigned sa = (unsigned)__cvta_generic_to_shared(s);
    asm volatile("cp.async.cg.shared.global [%0], [%1], 16;\n" :: "r"(sa), "l"(g));
}
__device__ __forceinline__ void cpa16z(void* s, const void* g, bool pred)
{
    unsigned sa = (unsigned)__cvta_generic_to_shared(s);
    int sz = pred ? 16 : 0;
    asm volatile("cp.async.cg.shared.global [%0], [%1], 16, %2;\n" :: "r"(sa), "l"(g), "r"(sz));
}
__device__ __forceinline__ void cp_commit() { asm volatile("cp.async.commit_group;\n"); }

template<int EPI>
__device__ __forceinline__ float epi_apply(float v, const float* bias, int n)
{
    if (EPI == 1)      v = fmaxf(v + bias[n], 0.f);
    else if (EPI == 2) v = v + bias[n];
    else if (EPI == 3) { v += bias[n]; v = (v > 20.f) ? v : log1pf(expf(v)); }
    return v;
}

// ---------------- split / reduce kernels ----------------
__global__ void split_w_kernel(const float* __restrict__ W, fp16* __restrict__ WS, size_t total)
{
    size_t idx = (size_t)blockIdx.x * blockDim.x + threadIdx.x;
    if (idx >= total) return;
    WS[idx] = __float2half(W[idx]);
}

// sum 4 split-K partial slabs -> g_xdbl; also emit planar hi/lo of the dt columns
__global__ void reduce_xdbl_kernel()
{
    size_t idx = (size_t)blockIdx.x * blockDim.x + threadIdx.x;
    const size_t S = (size_t)MROWS * XDBLW;
    if (idx >= S) return;
    float v = g_xdblp[idx] + g_xdblp[idx + S] + g_xdblp[idx + 2*S] + g_xdblp[idx + 3*S];
    g_xdbl[idx] = v;
    int col = (int)(idx % XDBLW);
    if (col < DTRANK) {
        size_t row = idx / XDBLW;
        size_t o = row * DTRANK + col;
        fp16 h = __float2half(v);
        g_xdblh[o] = h;
        g_xdbll[o] = __float2half(v - __half2float(h));
    }
}

// ------------- planar fp16 GEMM: C = (Ah [+ Al]) * W^T -------------
// LO=true: two-pass (hi+lo) A; LO=false: hi-only (half MMAs, 2 smem planes).
// Split-K: gridDim.z slabs, koff = z*Klen, C offset z*zcstride.
template<int EPI, bool LO>
__global__ void __launch_bounds__(128, 2)
gemm_mma(const fp16* __restrict__ Ah, const fp16* __restrict__ Al,
         const fp16* __restrict__ W, const float* __restrict__ bias,
         float* __restrict__ C, fp16* __restrict__ CSh, fp16* __restrict__ CSl,
         int Nv, int Nsplit, int Kstride, int Klen, size_t zcstride)
{
    extern __shared__ fp16 sm[];
    const int tid  = threadIdx.x;
    const int lane = tid & 31;
    const int w    = tid >> 5;
    const int bm   = blockIdx.y * TM;
    const int bn   = blockIdx.x * TN;
    const int wm   = (w & 1) * 64;
    const int wn   = (w >> 1) * 64;
    const int koff = blockIdx.z * Klen;
    if (C) C += (size_t)blockIdx.z * zcstride;

    const int a_r = lane & 15, a_c = (lane >> 4) * 8;
    const int b_r = (lane & 7) + ((lane >> 4) << 3), b_c = ((lane >> 3) & 1) * 8;

    const int NPLANES = LO ? 3 : 2;
    const int STG = NPLANES * PL;

    float acc[4][8][4];
#pragma unroll
    for (int i = 0; i < 4; i++)
#pragma unroll
        for (int j = 0; j < 8; j++)
#pragma unroll
            for (int q = 0; q < 4; q++) acc[i][j][q] = 0.f;

    const int nk = Klen / KC;

    auto fill = [&](int kc, int st) {
        fp16* sAh = sm + st * STG;
        fp16* sAl = sAh + PL;
        fp16* sB  = sAh + (NPLANES - 1) * PL;
#pragma unroll
        for (int i = 0; i < 4; i++) {
            int s = tid + i * 128;
            int row = s >> 2, c = (s & 3) * 8;
            size_t go = (size_t)(bm + row) * Kstride + koff + kc * KC + c;
            cpa16(&sAh[row * SKW + c], Ah + go);
            if (LO) cpa16(&sAl[row * SKW + c], Al + go);
            bool ok = (bn + row) < Nv;
            cpa16z(&sB[row * SKW + c],
                   W + (size_t)(ok ? (bn + row) : 0) * Kstride + koff + kc * KC + c, ok);
        }
        cp_commit();
    };

    fill(0, 0);
    if (nk > 1) fill(1, 1);

    for (int kb = 0; kb < nk; kb++) {
        if (kb + 2 < nk) { fill(kb + 2, (kb + 2) % STAGES); asm volatile("cp.async.wait_group 2;\n"); }
        else if (kb + 1 < nk) asm volatile("cp.async.wait_group 1;\n");
        else asm volatile("cp.async.wait_group 0;\n");
        __syncthreads();

        fp16* sAh = sm + (kb % STAGES) * STG;
        fp16* sAl = sAh + PL;
        fp16* sB  = sAh + (NPLANES - 1) * PL;
#pragma unroll
        for (int kk = 0; kk < KC; kk += 16) {
            unsigned bf[4][4];
#pragma unroll
            for (int p = 0; p < 4; p++)
                ldsm4(bf[p][0], bf[p][1], bf[p][2], bf[p][3],
                      &sB[(wn + p * 16 + b_r) * SKW + kk + b_c]);
            unsigned ah[4][4];
#pragma unroll
            for (int mi = 0; mi < 4; mi++)
                ldsm4(ah[mi][0], ah[mi][1], ah[mi][2], ah[mi][3],
                      &sAh[(wm + mi * 16 + a_r) * SKW + kk + a_c]);
#pragma unroll
            for (int mi = 0; mi < 4; mi++)
#pragma unroll
                for (int p = 0; p < 4; p++) {
                    mma16816(acc[mi][2 * p],     ah[mi], bf[p]);
                    mma16816(acc[mi][2 * p + 1], ah[mi], bf[p] + 2);
                }
            if (LO) {
                unsigned al[4][4];
#pragma unroll
                for (int mi = 0; mi < 4; mi++)
                    ldsm4(al[mi][0], al[mi][1], al[mi][2], al[mi][3],
                          &sAl[(wm + mi * 16 + a_r) * SKW + kk + a_c]);
#pragma unroll
                for (int mi = 0; mi < 4; mi++)
#pragma unroll
                    for (int p = 0; p < 4; p++) {
                        mma16816(acc[mi][2 * p],     al[mi], bf[p]);
                        mma16816(acc[mi][2 * p + 1], al[mi], bf[p] + 2);
                    }
            }
        }
        __syncthreads();
    }

    const int grp = lane >> 2, tq = lane & 3;
#pragma unroll
    for (int mi = 0; mi < 4; mi++)
#pragma unroll
        for (int nj = 0; nj < 8; nj++) {
            float* d = acc[mi][nj];
            int r0 = bm + wm + mi * 16 + grp;
            int c  = bn + wn + nj * 8 + tq * 2;
#pragma unroll
            for (int q = 0; q < 4; q++) {
                int r = r0 + (q >> 1) * 8;
                int cc = c + (q & 1);
                if (cc < Nv) {
                    float v = epi_apply<EPI>(d[q], bias, cc);
                    if (C) C[(size_t)r * Nv + cc] = v;
                    if (CSh && cc < Nsplit) {
                        fp16 h = __float2half(v);
                        size_t o = (size_t)r * Nsplit + cc;
                        CSh[o] = h;
                        if (CSl) CSl[o] = __float2half(v - __half2float(h));
                    }
                }
            }
        }
}

// ---------------- conv + silu: smem-tiled, coalesced ----------------
#define CBR 32
#define CBE 64
__global__ void __launch_bounds__(256)
conv_silu_kernel(const float* __restrict__ conv_w, const float* __restrict__ conv_b)
{
    __shared__ float su[CBR + 3][CBE];
    const int e0 = blockIdx.x * CBE;
    const int r0 = blockIdx.y * CBR;
    const int t  = threadIdx.x;
    const int te = t & (CBE - 1);
    const int bbase = (r0 / LL) * LL;

#pragma unroll
    for (int i = t >> 6; i < CBR + 3; i += 4) {
        int gr = r0 - 3 + i;
        su[i][te] = (gr >= bbase) ? g_xz[(size_t)gr * (2 * EI) + e0 + te] : 0.f;
    }
    __syncthreads();

    const int e = e0 + te;
    const float w0 = conv_w[e * DCONV], w1 = conv_w[e * DCONV + 1];
    const float w2 = conv_w[e * DCONV + 2], w3 = conv_w[e * DCONV + 3];
    const float bv = conv_b[e];
#pragma unroll
    for (int i = t >> 6; i < CBR; i += 4) {
        float s = bv + w0 * su[i][te] + w1 * su[i + 1][te]
                     + w2 * su[i + 2][te] + w3 * su[i + 3][te];
        float v = s / (1.f + expf(-s));
        size_t row = (size_t)(r0 + i);
        g_uc[row * EI + e] = v;
        fp16 h = __float2half(v);
        size_t o = row * EI + e;
        g_uch[o] = h;
        g_ucl[o] = __float2half(v - __half2float(h));
    }
}

// ---------------- selective scan: smem-staged, coalesced ----------------
#define SCH 64
__global__ void __launch_bounds__(512)
scan_kernel(const float* __restrict__ A_log, const float* __restrict__ Dp)
{
    __shared__ float s_dt[SCH][32], s_uc[SCH][32], s_z[SCH][32],
                     s_bc[SCH][32], s_y[SCH][32];
    const int b  = blockIdx.y;
    const int e0 = blockIdx.x * 32;
    const int t  = threadIdx.x;
    const int c  = t >> 4;
    const int n  = t & 15;
    const int e  = e0 + c;

    const float Aen = -expf(A_log[e * NSTATE + n]);
    const float Dv  = Dp[e];
    float h = 0.f;
    const size_t rb = (size_t)b * LL;

    for (int l0 = 0; l0 < LL; l0 += SCH) {
        for (int k = t; k < SCH * 32; k += 512) {
            int i = k >> 5, j = k & 31;
            size_t row = rb + l0 + i;
            s_dt[i][j] = g_dt[row * EI + e0 + j];
            s_uc[i][j] = g_uc[row * EI + e0 + j];
            s_z [i][j] = g_xz[row * (2 * EI) + EI + e0 + j];
            s_bc[i][j] = g_xdbl[row * XDBLW + DTRANK + j];
        }
        __syncthreads();

#pragma unroll 4
        for (int i = 0; i < SCH; i++) {
            float dtv = s_dt[i][c];
            float uv  = s_uc[i][c];
            float Bt  = s_bc[i][n];
            float Ct  = s_bc[i][16 + n];
            h = expf(dtv * Aen) * h + dtv * uv * Bt;
            float p = h * Ct;
            p += __shfl_xor_sync(0xffffffffu, p, 8);
            p += __shfl_xor_sync(0xffffffffu, p, 4);
            p += __shfl_xor_sync(0xffffffffu, p, 2);
            p += __shfl_xor_sync(0xffffffffu, p, 1);
            if (n == 0) {
                float zv = s_z[i][c];
                s_y[i][c] = (p + uv * Dv) * (zv / (1.f + expf(-zv)));
            }
        }
        __syncthreads();

        for (int k = t; k < SCH * 32; k += 512) {
            int i = k >> 5, j = k & 31;
            size_t row = rb + l0 + i;
            g_ysh[row * EI + e0 + j] = __float2half(s_y[i][j]);
        }
        __syncthreads();
    }
}

// ---------------- host launch ----------------
extern "C" void kernel_launch(void* const* d_in, const int* in_sizes, int n_in,
                              void* d_out, int out_size)
{
    const float* x          = (const float*)d_in[0];
    const float* in_proj_w  = (const float*)d_in[1];
    const float* conv_w     = (const float*)d_in[2];
    const float* conv_b     = (const float*)d_in[3];
    const float* x_proj_w   = (const float*)d_in[4];
    const float* dt_proj_w  = (const float*)d_in[5];
    const float* dt_proj_b  = (const float*)d_in[6];
    const float* A_log      = (const float*)d_in[7];
    const float* Dp         = (const float*)d_in[8];
    const float* out_proj_w = (const float*)d_in[9];
    const float* lin1_w     = (const float*)d_in[10];
    const float* lin1_b     = (const float*)d_in[11];
    const float* lin2_w     = (const float*)d_in[12];
    const float* lin2_b     = (const float*)d_in[13];
    float* out = (float*)d_out;

    float *p_xz, *p_xdbl, *p_xdblp, *p_dt;
    fp16 *p_xsh,*p_uch,*p_ucl,*p_xdh,*p_xdl,*p_ysh,*p_y2h,*p_hsh;
    fp16 *p_win,*p_wxp,*p_wdt,*p_wout,*p_wl1,*p_wl2;
    cudaGetSymbolAddress((void**)&p_xz,    g_xz);
    cudaGetSymbolAddress((void**)&p_xdbl,  g_xdbl);
    cudaGetSymbolAddress((void**)&p_xdblp, g_xdblp);
    cudaGetSymbolAddress((void**)&p_dt,    g_dt);
    cudaGetSymbolAddress((void**)&p_xsh,   g_xsh);
    cudaGetSymbolAddress((void**)&p_uch,   g_uch);  cudaGetSymbolAddress((void**)&p_ucl, g_ucl);
    cudaGetSymbolAddress((void**)&p_xdh,   g_xdblh);cudaGetSymbolAddress((void**)&p_xdl, g_xdbll);
    cudaGetSymbolAddress((void**)&p_ysh,   g_ysh);
    cudaGetSymbolAddress((void**)&p_y2h,   g_y2sh);
    cudaGetSymbolAddress((void**)&p_hsh,   g_hsh);
    cudaGetSymbolAddress((void**)&p_win,   g_win);
    cudaGetSymbolAddress((void**)&p_wxp,   g_wxp);
    cudaGetSymbolAddress((void**)&p_wdt,   g_wdt);
    cudaGetSymbolAddress((void**)&p_wout,  g_wout);
    cudaGetSymbolAddress((void**)&p_wl1,   g_wl1);
    cudaGetSymbolAddress((void**)&p_wl2,   g_wl2);

    cudaFuncSetAttribute((const void*)gemm_mma<0,false>, cudaFuncAttributeMaxDynamicSharedMemorySize, GSMEM);
    cudaFuncSetAttribute((const void*)gemm_mma<0,true>,  cudaFuncAttributeMaxDynamicSharedMemorySize, GSMEM);
    cudaFuncSetAttribute((const void*)gemm_mma<3,true>,  cudaFuncAttributeMaxDynamicSharedMemorySize, GSMEM);
    cudaFuncSetAttribute((const void*)gemm_mma<1,false>, cudaFuncAttributeMaxDynamicSharedMemorySize, GSMEM);
    cudaFuncSetAttribute((const void*)gemm_mma<2,false>, cudaFuncAttributeMaxDynamicSharedMemorySize, GSMEM);

    const int GY = MROWS / TM;   // 64
    size_t t;

    // idx0-2: splits; idx3 = in_proj GEMM (profiled)
    t = (size_t)MROWS * DMODEL;
    split_w_kernel<<<(unsigned)((t + 255) / 256), 256>>>(x, p_xsh, t);
    t = (size_t)(2 * EI) * DMODEL;
    split_w_kernel<<<(unsigned)((t + 255) / 256), 256>>>(in_proj_w, p_win, t);
    t = (size_t)XDBLW * EI;
    split_w_kernel<<<(unsigned)((t + 255) / 256), 256>>>(x_proj_w, p_wxp, t);

    // idx3: xz = x @ in_proj_w^T (hi only) -> fp32 g_xz
    gemm_mma<0,false><<<dim3((2 * EI) / TN, GY), 128, GSMEM>>>(
        p_xsh, (const fp16*)0, p_win, (const float*)0, p_xz, (fp16*)0, (fp16*)0,
        2 * EI, 0, DMODEL, DMODEL, 0);

    // conv + silu
    conv_silu_kernel<<<dim3(EI / CBE, MROWS / CBR), 256>>>(conv_w, conv_b);

    // x_dbl partials: 4-way split-K (hi+lo), each z writes its own slab
    gemm_mma<0,true><<<dim3(1, GY, 4), 128, GSMEM>>>(
        p_uch, p_ucl, p_wxp, (const float*)0, p_xdblp, (fp16*)0, (fp16*)0,
        XDBLW, 0, EI, EI / 4, (size_t)MROWS * XDBLW);

    // reduce partials -> g_xdbl + planar dt-col split
    reduce_xdbl_kernel<<<(unsigned)(((size_t)MROWS * XDBLW + 255) / 256), 256>>>();

    t = (size_t)EI * DTRANK;
    split_w_kernel<<<(unsigned)((t + 255) / 256), 256>>>(dt_proj_w, p_wdt, t);

    // dt = softplus(dt_raw @ dt_proj_w^T + b) (hi+lo)
    gemm_mma<3,true><<<dim3(EI / TN, GY), 128, GSMEM>>>(
        p_xdh, p_xdl, p_wdt, dt_proj_b, p_dt, (fp16*)0, (fp16*)0,
        EI, 0, DTRANK, DTRANK, 0);

    // selective scan -> ysh
    scan_kernel<<<dim3(EI / 32, BB), 512>>>(A_log, Dp);

    t = (size_t)DMODEL * EI;
    split_w_kernel<<<(unsigned)((t + 255) / 256), 256>>>(out_proj_w, p_wout, t);

    // y2 = y @ out_proj_w^T (hi only) -> y2sh only
    gemm_mma<0,false><<<dim3(DMODEL / TN, GY), 128, GSMEM>>>(
        p_ysh, (const fp16*)0, p_wout, (const float*)0, (float*)0, p_y2h, (fp16*)0,
        DMODEL, DMODEL, EI, EI, 0);

    t = (size_t)DFF * DMODEL;
    split_w_kernel<<<(unsigned)((t + 255) / 256), 256>>>(lin1_w, p_wl1, t);

    // h = relu(y2 @ lin1_w^T + b) (hi only) -> hsh only
    gemm_mma<1,false><<<dim3(DFF / TN, GY), 128, GSMEM>>>(
        p_y2h, (const fp16*)0, p_wl1, lin1_b, (float*)0, p_hsh, (fp16*)0,
        DFF, DFF, DMODEL, DMODEL, 0);

    t = (size_t)DMODEL * DFF;
    split_w_kernel<<<(unsigned)((t + 255) / 256), 256>>>(lin2_w, p_wl2, t);

    // out = h @ lin2_w^T + b (hi only) -> fp32 out
    gemm_mma<2,false><<<dim3(DMODEL / TN, GY), 128, GSMEM>>>(
        p_hsh, (const fp16*)0, p_wl2, lin2_b, out, (fp16*)0, (fp16*)0,
        DMODEL, 0, DFF, DFF, 0);
}